// round 17
// baseline (speedup 1.0000x reference)
#include <cuda_runtime.h>
#include <cuda_fp16.h>
#include <math.h>
#include <stdint.h>

#define NN 100000
#define EE 1600000
#define DH 128
#define DOUT 64
#define NCHUNK 98   // ceil(NN/1024)

// ---------------- scratch (device globals) ----------------
__device__ __half g_tl[(size_t)NN * DH];   // aggregation operand (fp16)
__device__ __half g_tr[(size_t)NN * DH];   // self term (fp16)
__device__ __half g_h1[(size_t)NN * DH];   // hidden activations (fp16)
__device__ __half g_h2[(size_t)NN * DH];
__device__ float  g_deginv[NN];
__device__ int    g_cnt[NN];
__device__ int    g_rowptr[NN];
__device__ int    g_cursor[NN];
__device__ int    g_col[EE];
__device__ int    g_gpos;

// ---------------- CSR build ----------------
__global__ void zero_cnt_kernel() {
    int i = blockIdx.x * blockDim.x + threadIdx.x;
    if (i < NN) g_cnt[i] = 0;
    if (i == 0) g_gpos = 0;
}

// single-kernel segment assignment: block base via global atomic cursor.
// (placement order is nondeterministic; per-node neighbor sets are invariant)
__global__ void emit_kernel() {
    __shared__ int sm[256];
    __shared__ int bbase;
    int b = blockIdx.x, t = threadIdx.x;
    int n0 = b * 1024 + t * 4;
    int c[4];
    int tsum = 0;
#pragma unroll
    for (int i = 0; i < 4; i++) {
        c[i] = (n0 + i < NN) ? g_cnt[n0 + i] : 0;
        tsum += c[i];
    }
    sm[t] = tsum;
    __syncthreads();
    for (int off = 1; off < 256; off <<= 1) {
        int add = (t >= off) ? sm[t - off] : 0;
        __syncthreads();
        sm[t] += add;
        __syncthreads();
    }
    if (t == 255) bbase = atomicAdd(&g_gpos, sm[255]);
    __syncthreads();
    int base = bbase + sm[t] - tsum;
#pragma unroll
    for (int i = 0; i < 4; i++) {
        int n = n0 + i;
        if (n < NN) {
            g_rowptr[n] = base;
            g_cursor[n] = base;
            g_deginv[n] = 1.0f / (float)max(c[i], 1);
            base += c[i];
        }
    }
}

__global__ void fill_kernel(const int* __restrict__ ei) {
    int e = blockIdx.x * blockDim.x + threadIdx.x;
    if (e < EE) {
        int d = ei[EE + e];
        int pos = atomicAdd(&g_cursor[d], 1);
        g_col[pos] = ei[e];
    }
}

// ---------------- fp16 helpers ----------------
__device__ __forceinline__ uint32_t pack_h2(float a, float b) {
    __half2 h = __floats2half2_rn(a, b);
    return *reinterpret_cast<uint32_t*>(&h);
}

__device__ __forceinline__ void mma_f32acc(float* c, uint32_t a0, uint32_t a1,
                                           uint32_t a2, uint32_t a3,
                                           uint32_t b0, uint32_t b1) {
    asm volatile(
        "mma.sync.aligned.m16n8k16.row.col.f32.f16.f16.f32 "
        "{%0,%1,%2,%3}, {%4,%5,%6,%7}, {%8,%9}, {%0,%1,%2,%3};\n"
        : "+f"(c[0]), "+f"(c[1]), "+f"(c[2]), "+f"(c[3])
        : "r"(a0), "r"(a1), "r"(a2), "r"(a3), "r"(b0), "r"(b1));
}

// ---------------- persistent dual GEMM, fp16 operands (1 MMA per k-step) ----------------
// Yl(fp16) = A@Wl, Yr(fp16) = A@Wr.
// HALFIN: A already fp16 (h1/h2) -> staging is a pure copy.
template <int BNH, bool HALFIN>
__global__ void __launch_bounds__((BNH == 128) ? 512 : 256, 1) gemm_persist(
    const void* __restrict__ Avoid, const float* __restrict__ Wl,
    const float* __restrict__ Wr, __half* __restrict__ Yl,
    __half* __restrict__ Yr, int M, const int* __restrict__ ei, int doHist) {
    constexpr int N2 = 2 * BNH;
    constexpr int THREADS = (BNH == 128) ? 512 : 256;
    constexpr int NTG = N2 / 8;                 // global n-tiles
    constexpr int BUNITS = 8 * NTG * 32;        // B uint4 count
    constexpr int AUNITS = 8 * 4 * 2 * 32;      // 2048 uint4
    constexpr int BITER = BUNITS / THREADS;
    constexpr int AITER = AUNITS / THREADS;

    extern __shared__ uint4 smu[];
    uint4* Bfr  = smu;                 // [BUNITS]
    uint4* Ahi  = smu + BUNITS;        // [AUNITS]

    const int tid = threadIdx.x;
    const int lane = tid & 31, wid = tid >> 5;
    const int wm = wid & 3, wn = wid >> 2;      // warp tile 32m x 64n
    const int g = lane >> 2, tig = lane & 3;

    // ---- fused edge histogram (L1 only) ----
    if (doHist) {
        for (int e = blockIdx.x * THREADS + tid; e < EE; e += gridDim.x * THREADS)
            atomicAdd(&g_cnt[ei[EE + e]], 1);
    }

    // ---- stage B once per CTA (fragment order) ----
#pragma unroll
    for (int it = 0; it < BITER; it++) {
        int u = tid + it * THREADS;
        int c = u / (NTG * 32);
        int rem = u % (NTG * 32);
        int ntg = rem >> 5;
        int l = rem & 31;
        int lg = l >> 2, ltig = l & 3;
        int n = ntg * 8 + lg;
        const float* Wp = (n < BNH) ? Wl : Wr;
        int col = (n < BNH) ? n : n - BNH;
        int k0 = c * 16 + 2 * ltig;
        int k1 = k0 + 8;
        uint32_t b0 = pack_h2(Wp[(size_t)k0 * BNH + col], Wp[(size_t)(k0 + 1) * BNH + col]);
        uint32_t b1 = pack_h2(Wp[(size_t)k1 * BNH + col], Wp[(size_t)(k1 + 1) * BNH + col]);
        Bfr[u] = make_uint4(b0, b1, 0u, 0u);
    }

    const int ntiles = (M + 127) / 128;
    for (int tile = blockIdx.x; tile < ntiles; tile += gridDim.x) {
        const int m_blk = tile * 128;
        __syncthreads();   // prior tile's reads done

        // ---- stage A tile (fragment order, fp16) ----
#pragma unroll
        for (int it = 0; it < AITER; it++) {
            int u = tid + it * THREADS;
            int c = u >> 8;
            int rem = u & 255;
            int lwm = rem >> 6;
            int lmt = (rem >> 5) & 1;
            int l = rem & 31;
            int lg = l >> 2, ltig = l & 3;
            int r0 = lwm * 32 + lmt * 16 + lg;
            int m0 = m_blk + r0, m1 = m0 + 8;
            int k0 = c * 16 + 2 * ltig;
            if constexpr (HALFIN) {
                const __half* Ah = (const __half*)Avoid;
                uint32_t w00 = 0, w01 = 0, w10 = 0, w11 = 0;
                if (m0 < M) {
                    w00 = *(const uint32_t*)&Ah[(size_t)m0 * DH + k0];
                    w01 = *(const uint32_t*)&Ah[(size_t)m0 * DH + k0 + 8];
                }
                if (m1 < M) {
                    w10 = *(const uint32_t*)&Ah[(size_t)m1 * DH + k0];
                    w11 = *(const uint32_t*)&Ah[(size_t)m1 * DH + k0 + 8];
                }
                Ahi[u] = make_uint4(w00, w10, w01, w11);
            } else {
                const float* A = (const float*)Avoid;
                float2 v00 = make_float2(0.f, 0.f), v01 = v00, v10 = v00, v11 = v00;
                if (m0 < M) {
                    v00 = *(const float2*)&A[(size_t)m0 * DH + k0];
                    v01 = *(const float2*)&A[(size_t)m0 * DH + k0 + 8];
                }
                if (m1 < M) {
                    v10 = *(const float2*)&A[(size_t)m1 * DH + k0];
                    v11 = *(const float2*)&A[(size_t)m1 * DH + k0 + 8];
                }
                Ahi[u] = make_uint4(pack_h2(v00.x, v00.y), pack_h2(v10.x, v10.y),
                                    pack_h2(v01.x, v01.y), pack_h2(v11.x, v11.y));
            }
        }
        __syncthreads();

        // ---- MMA sweep: 1 MMA per (c, nt, mt) ----
        float acc[2][8][4];
#pragma unroll
        for (int mt = 0; mt < 2; mt++)
#pragma unroll
            for (int nt = 0; nt < 8; nt++)
#pragma unroll
                for (int j = 0; j < 4; j++) acc[mt][nt][j] = 0.f;

#pragma unroll
        for (int c = 0; c < 8; c++) {
            uint4 ah[2];
#pragma unroll
            for (int mt = 0; mt < 2; mt++) {
                int u = ((c * 4 + wm) * 2 + mt) * 32 + lane;
                ah[mt] = Ahi[u];
            }
#pragma unroll
            for (int nt = 0; nt < 8; nt++) {
                int ntg = wn * 8 + nt;
                uint4 bu = Bfr[(c * NTG + ntg) * 32 + lane];
#pragma unroll
                for (int mt = 0; mt < 2; mt++) {
                    mma_f32acc(acc[mt][nt], ah[mt].x, ah[mt].y, ah[mt].z, ah[mt].w, bu.x, bu.y);
                }
            }
        }

        // ---- epilogue (both outputs fp16) ----
#pragma unroll
        for (int mt = 0; mt < 2; mt++) {
            int r0 = m_blk + wm * 32 + mt * 16 + g;
#pragma unroll
            for (int nt = 0; nt < 8; nt++) {
                int n2 = wn * 64 + nt * 8 + 2 * tig;
                __half* Y = (n2 < BNH) ? Yl : Yr;
                int colb = (n2 < BNH) ? n2 : n2 - BNH;
                if (r0 < M)
                    *(__half2*)&Y[(size_t)r0 * BNH + colb] =
                        __floats2half2_rn(acc[mt][nt][0], acc[mt][nt][1]);
                if (r0 + 8 < M)
                    *(__half2*)&Y[(size_t)(r0 + 8) * BNH + colb] =
                        __floats2half2_rn(acc[mt][nt][2], acc[mt][nt][3]);
            }
        }
    }
}

// ---------------- aggregate width 128: HALF-WARP per node ----------------
__global__ void agg_combine128(const __half* __restrict__ tl, const __half* __restrict__ tr,
                               const float* __restrict__ bias, __half* __restrict__ out) {
    int node = (blockIdx.x * blockDim.x + threadIdx.x) >> 4;
    if (node >= NN) return;
    int lane = threadIdx.x & 31;
    int hl = lane & 15;
    int hbase = lane & 16;
    unsigned hmask = 0xFFFFu << hbase;
    int start = g_rowptr[node];
    int cnt = g_cnt[node];
    float a0 = 0.f, a1 = 0.f, a2 = 0.f, a3 = 0.f, a4 = 0.f, a5 = 0.f, a6 = 0.f, a7 = 0.f;
    int j = 0;
    while (j < cnt) {
        int batch = min(cnt - j, 16);
        int s = (hl < batch) ? g_col[start + j + hl] : 0;
        int t = 0;
        for (; t + 4 <= batch; t += 4) {
            int s0 = __shfl_sync(hmask, s, hbase + t);
            int s1 = __shfl_sync(hmask, s, hbase + t + 1);
            int s2 = __shfl_sync(hmask, s, hbase + t + 2);
            int s3 = __shfl_sync(hmask, s, hbase + t + 3);
            uint4 u0 = *(const uint4*)&tl[(size_t)s0 * DH + hl * 8];
            uint4 u1 = *(const uint4*)&tl[(size_t)s1 * DH + hl * 8];
            uint4 u2 = *(const uint4*)&tl[(size_t)s2 * DH + hl * 8];
            uint4 u3 = *(const uint4*)&tl[(size_t)s3 * DH + hl * 8];
            float2 f;
            f = __half22float2(*(__half2*)&u0.x); a0 += f.x; a1 += f.y;
            f = __half22float2(*(__half2*)&u0.y); a2 += f.x; a3 += f.y;
            f = __half22float2(*(__half2*)&u0.z); a4 += f.x; a5 += f.y;
            f = __half22float2(*(__half2*)&u0.w); a6 += f.x; a7 += f.y;
            f = __half22float2(*(__half2*)&u1.x); a0 += f.x; a1 += f.y;
            f = __half22float2(*(__half2*)&u1.y); a2 += f.x; a3 += f.y;
            f = __half22float2(*(__half2*)&u1.z); a4 += f.x; a5 += f.y;
            f = __half22float2(*(__half2*)&u1.w); a6 += f.x; a7 += f.y;
            f = __half22float2(*(__half2*)&u2.x); a0 += f.x; a1 += f.y;
            f = __half22float2(*(__half2*)&u2.y); a2 += f.x; a3 += f.y;
            f = __half22float2(*(__half2*)&u2.z); a4 += f.x; a5 += f.y;
            f = __half22float2(*(__half2*)&u2.w); a6 += f.x; a7 += f.y;
            f = __half22float2(*(__half2*)&u3.x); a0 += f.x; a1 += f.y;
            f = __half22float2(*(__half2*)&u3.y); a2 += f.x; a3 += f.y;
            f = __half22float2(*(__half2*)&u3.z); a4 += f.x; a5 += f.y;
            f = __half22float2(*(__half2*)&u3.w); a6 += f.x; a7 += f.y;
        }
        for (; t < batch; t++) {
            int sv = __shfl_sync(hmask, s, hbase + t);
            uint4 u0 = *(const uint4*)&tl[(size_t)sv * DH + hl * 8];
            float2 f;
            f = __half22float2(*(__half2*)&u0.x); a0 += f.x; a1 += f.y;
            f = __half22float2(*(__half2*)&u0.y); a2 += f.x; a3 += f.y;
            f = __half22float2(*(__half2*)&u0.z); a4 += f.x; a5 += f.y;
            f = __half22float2(*(__half2*)&u0.w); a6 += f.x; a7 += f.y;
        }
        j += batch;
    }
    float sc = g_deginv[node];
    float4 b0 = *(const float4*)&bias[hl * 8];
    float4 b1 = *(const float4*)&bias[hl * 8 + 4];
    uint4 rr = *(const uint4*)&tr[(size_t)node * DH + hl * 8];
    float2 r0 = __half22float2(*(__half2*)&rr.x);
    float2 r1 = __half22float2(*(__half2*)&rr.y);
    float2 r2 = __half22float2(*(__half2*)&rr.z);
    float2 r3 = __half22float2(*(__half2*)&rr.w);
    float y0 = fmaxf(a0 * sc + b0.x + r0.x, 0.f);
    float y1 = fmaxf(a1 * sc + b0.y + r0.y, 0.f);
    float y2 = fmaxf(a2 * sc + b0.z + r1.x, 0.f);
    float y3 = fmaxf(a3 * sc + b0.w + r1.y, 0.f);
    float y4 = fmaxf(a4 * sc + b1.x + r2.x, 0.f);
    float y5 = fmaxf(a5 * sc + b1.y + r2.y, 0.f);
    float y6 = fmaxf(a6 * sc + b1.z + r3.x, 0.f);
    float y7 = fmaxf(a7 * sc + b1.w + r3.y, 0.f);
    uint4 o;
    o.x = pack_h2(y0, y1);
    o.y = pack_h2(y2, y3);
    o.z = pack_h2(y4, y5);
    o.w = pack_h2(y6, y7);
    *(uint4*)&out[(size_t)node * DH + hl * 8] = o;
}

// ---------------- layer-3: aggregate (width 64, fp16) + bias + self + L2 normalize ----------------
__global__ void agg_norm64(const __half* __restrict__ tl, const __half* __restrict__ tr,
                           const float* __restrict__ bias, float* __restrict__ out) {
    int node = (blockIdx.x * blockDim.x + threadIdx.x) >> 5;
    int lane = threadIdx.x & 31;
    if (node >= NN) return;
    int start = g_rowptr[node];
    int cnt = g_cnt[node];
    float ax = 0.f, ay = 0.f;
    int j = 0;
    while (j < cnt) {
        int batch = min(cnt - j, 32);
        int s = (lane < batch) ? g_col[start + j + lane] : 0;
        int t = 0;
        for (; t + 4 <= batch; t += 4) {
            int s0 = __shfl_sync(0xffffffffu, s, t);
            int s1 = __shfl_sync(0xffffffffu, s, t + 1);
            int s2 = __shfl_sync(0xffffffffu, s, t + 2);
            int s3 = __shfl_sync(0xffffffffu, s, t + 3);
            float2 v0 = __half22float2(*(const __half2*)&tl[(size_t)s0 * DOUT + lane * 2]);
            float2 v1 = __half22float2(*(const __half2*)&tl[(size_t)s1 * DOUT + lane * 2]);
            float2 v2 = __half22float2(*(const __half2*)&tl[(size_t)s2 * DOUT + lane * 2]);
            float2 v3 = __half22float2(*(const __half2*)&tl[(size_t)s3 * DOUT + lane * 2]);
            ax += v0.x + v1.x + v2.x + v3.x;
            ay += v0.y + v1.y + v2.y + v3.y;
        }
        for (; t < batch; t++) {
            int sv = __shfl_sync(0xffffffffu, s, t);
            float2 v = __half22float2(*(const __half2*)&tl[(size_t)sv * DOUT + lane * 2]);
            ax += v.x; ay += v.y;
        }
        j += batch;
    }
    float sc = g_deginv[node];
    float2 b = *(const float2*)&bias[lane * 2];
    float2 r = __half22float2(*(const __half2*)&tr[(size_t)node * DOUT + lane * 2]);
    float yx = ax * sc + b.x + r.x;
    float yy = ay * sc + b.y + r.y;
    float ss = yx * yx + yy * yy;
#pragma unroll
    for (int off = 16; off > 0; off >>= 1) ss += __shfl_xor_sync(0xffffffffu, ss, off);
    float inv = 1.0f / fmaxf(sqrtf(ss), 1e-12f);
    *(float2*)&out[(size_t)node * DOUT + lane * 2] = make_float2(yx * inv, yy * inv);
}

// ---------------- launch ----------------
extern "C" void kernel_launch(void* const* d_in, const int* in_sizes, int n_in,
                              void* d_out, int out_size) {
    const float* x   = (const float*)d_in[0];
    const int*   ei  = (const int*)d_in[1];
    const float* Wl1 = (const float*)d_in[2];
    const float* bl1 = (const float*)d_in[3];
    const float* Wr1 = (const float*)d_in[4];
    const float* Wl2 = (const float*)d_in[5];
    const float* bl2 = (const float*)d_in[6];
    const float* Wr2 = (const float*)d_in[7];
    const float* Wl3 = (const float*)d_in[8];
    const float* bl3 = (const float*)d_in[9];
    const float* Wr3 = (const float*)d_in[10];
    float* out = (float*)d_out;

    void *ptl, *ptr, *p1, *p2;
    cudaGetSymbolAddress(&ptl, g_tl);
    cudaGetSymbolAddress(&ptr, g_tr);
    cudaGetSymbolAddress(&p1, g_h1);
    cudaGetSymbolAddress(&p2, g_h2);
    __half* tl = (__half*)ptl;
    __half* tr = (__half*)ptr;
    __half* h1 = (__half*)p1;
    __half* h2 = (__half*)p2;

    const int SMEM128 = 8 * 32 * 32 * 16 + 32768;   // B 131072 + A 32768 = 163840
    const int SMEM64  = 8 * 16 * 32 * 16 + 32768;   // B 65536 + A 32768 = 98304
    cudaFuncSetAttribute(gemm_persist<128, false>, cudaFuncAttributeMaxDynamicSharedMemorySize, SMEM128);
    cudaFuncSetAttribute(gemm_persist<128, true>,  cudaFuncAttributeMaxDynamicSharedMemorySize, SMEM128);
    cudaFuncSetAttribute(gemm_persist<64, true>,   cudaFuncAttributeMaxDynamicSharedMemorySize, SMEM64);

    const int AB128 = (NN + 15) / 16;
    const int AB = (NN + 7) / 8;
    const int PERS = 148;

    zero_cnt_kernel<<<(NN + 255) / 256, 256>>>();
    gemm_persist<128, false><<<PERS, 512, SMEM128>>>(x, Wl1, Wr1, tl, tr, NN, ei, 1);  // fused hist
    emit_kernel<<<NCHUNK, 256>>>();
    fill_kernel<<<(EE + 255) / 256, 256>>>(ei);

    // layer 1 aggregate
    agg_combine128<<<AB128, 256>>>(tl, tr, bl1, h1);
    // layer 2
    gemm_persist<128, true><<<PERS, 512, SMEM128>>>(h1, Wl2, Wr2, tl, tr, NN, ei, 0);
    agg_combine128<<<AB128, 256>>>(tl, tr, bl2, h2);
    // layer 3 (width 64) + fused L2 normalize
    gemm_persist<64, true><<<PERS, 256, SMEM64>>>(h2, Wl3, Wr3, tl, tr, NN, ei, 0);
    agg_norm64<<<AB, 256>>>(tl, tr, bl3, out);
}